// round 8
// baseline (speedup 1.0000x reference)
#include <cuda_runtime.h>
#include <math.h>

// Problem shape (fixed by setup_inputs)
#define BATCH 256
#define TLEN  1024
#define DDIM  256
#define LOG2PI 1.8378770664093453f

// Main-kernel tiling
#define GBTOT   16                // batches per block (4 quarters x 4)
#define GBQ     4                 // batches per thread (quarter)
#define NCHUNK  64                // t-chunks
#define CHUNK   (TLEN / NCHUNK)   // 16 (uniform: t=0 folded into table row 0)
#define BSTRIDE (TLEN * DDIM)     // elements between batches (1MB)

// Table: 3 SoA sections of TLEN*DDIM floats; row 0 encodes the initial term
// (A=0, R=1/sqrt(var0), C=-mu/sqrt(var0)), rows t>=1 the transitions.
#define SEC    (TLEN * DDIM)
#define SEC_A  0
#define SEC_R  SEC
#define SEC_C  (2 * SEC)
__device__ float g_tabf[3 * SEC];
__device__ float g_row[TLEN];       // per-t row sums of log q + LOG2PI

__device__ __forceinline__ float softplusf(float x) {
    return (x > 20.f) ? x : log1pf(expf(x));
}

// ---------------------------------------------------------------------------
// Kernel 1: precompute table + per-row log constants; zero the output.
// grid = TLEN blocks, block = DDIM threads
// ---------------------------------------------------------------------------
__global__ void k_precompute(const float* __restrict__ ts,
                             const float* __restrict__ log_kappa,
                             const float* __restrict__ log_sigma,
                             const float* __restrict__ mu,
                             float* __restrict__ out, int out_size) {
    const int t = blockIdx.x;
    const int d = threadIdx.x;

    float kappa = softplusf(log_kappa[d]) + 1e-6f;
    float sigma = softplusf(log_sigma[d]) + 1e-6f;
    float s2 = sigma * sigma;
    float mu_d = mu[d];

    float elem;
    const int idx = t * DDIM + d;
    if (t == 0) {
        float var0 = fmaxf(s2 / (2.0f * kappa), 1e-10f);
        float r0 = rsqrtf(var0);
        g_tabf[SEC_A + idx] = 0.0f;          // zero out prev contribution
        g_tabf[SEC_R + idx] = r0;
        g_tabf[SEC_C + idx] = -mu_d * r0;
        elem = logf(var0) + LOG2PI;
        for (int i = d; i < out_size; i += blockDim.x) out[i] = 0.0f;
    } else {
        float dt = fmaxf(ts[t * DDIM + d] - ts[(t - 1) * DDIM + d], 1e-6f);
        float Ad = expf(-kappa * dt);
        float q  = fmaxf(s2 * (-expm1f(-2.0f * kappa * dt)) / (2.0f * kappa), 1e-10f);
        float R  = rsqrtf(q);
        g_tabf[SEC_A + idx] = Ad;
        g_tabf[SEC_R + idx] = R;
        g_tabf[SEC_C + idx] = -mu_d * (1.0f - Ad) * R;
        elem = logf(q) + LOG2PI;
    }

    __shared__ float sm[DDIM];
    sm[d] = elem;
    __syncthreads();
    for (int s = DDIM / 2; s > 0; s >>= 1) {
        if (d < s) sm[d] += sm[d + s];
        __syncthreads();
    }
    if (d == 0) g_row[t] = sm[0];
}

// ---------------------------------------------------------------------------
// Kernel 2: main streaming pass. grid = 1024 blocks, block = 256 threads.
// dq = tid&63 covers d = {4dq..4dq+3}; h = tid>>6 handles GBQ=4 batches.
// One table read per t-row now serves 16 batches (block-level) -> table L2
// traffic halved vs GBTOT=8. Front-batched 2t windows of LDG.128.
// ---------------------------------------------------------------------------
__global__ __launch_bounds__(256, 3)
void k_main(const float* __restrict__ y, float* __restrict__ out) {
    const int c     = blockIdx.x & (NCHUNK - 1);
    const int bbase = (blockIdx.x >> 6) * GBTOT;
    const int tid   = threadIdx.x;
    const int dq    = tid & 63;
    const int h     = tid >> 6;

    const float* __restrict__ yb =
        y + (size_t)(bbase + h * GBQ) * BSTRIDE + 4 * dq;

    const int tstart = c * CHUNK;
    const int prow   = (c == 0) ? 0 : tstart - 1;  // value unused at c==0 (A=0)

    float4 prev[GBQ];
    float  acc[GBQ];
#pragma unroll
    for (int g = 0; g < GBQ; g++) {
        prev[g] = __ldcs((const float4*)(yb + (size_t)prow * DDIM + g * BSTRIDE));
        acc[g]  = 0.0f;
    }

    const float* __restrict__ yt0 = yb + (size_t)tstart * DDIM;
    const float* __restrict__ tt0 = g_tabf + 4 * dq + (size_t)tstart * DDIM;

#pragma unroll
    for (int i = 0; i < CHUNK / 2; i++) {
        // ---- front-batched y loads: 8 LDG.128 back-to-back ----
        float4 yv[2][GBQ];
#pragma unroll
        for (int u = 0; u < 2; u++)
#pragma unroll
            for (int g = 0; g < GBQ; g++)
                yv[u][g] = __ldcs((const float4*)(yt0 + (2 * i + u) * DDIM
                                                  + g * BSTRIDE));
        // ---- per-step table loads (L2 hits) + compute ----
#pragma unroll
        for (int u = 0; u < 2; u++) {
            const float* tt = tt0 + (2 * i + u) * DDIM;
            float4 A  = __ldg((const float4*)(tt + SEC_A));
            float4 R  = __ldg((const float4*)(tt + SEC_R));
            float4 Cc = __ldg((const float4*)(tt + SEC_C));
#pragma unroll
            for (int g = 0; g < GBQ; g++) {
                float x0 = fmaf(-A.x, prev[g].x, yv[u][g].x);
                float x1 = fmaf(-A.y, prev[g].y, yv[u][g].y);
                float x2 = fmaf(-A.z, prev[g].z, yv[u][g].z);
                float x3 = fmaf(-A.w, prev[g].w, yv[u][g].w);
                float z0 = fmaf(x0, R.x, Cc.x);
                float z1 = fmaf(x1, R.y, Cc.y);
                float z2 = fmaf(x2, R.z, Cc.z);
                float z3 = fmaf(x3, R.w, Cc.w);
                acc[g] = fmaf(z0, z0, acc[g]);
                acc[g] = fmaf(z1, z1, acc[g]);
                acc[g] = fmaf(z2, z2, acc[g]);
                acc[g] = fmaf(z3, z3, acc[g]);
                prev[g] = yv[u][g];
            }
        }
    }

    // ---- reduce: warp shuffle per g, cross-warp via smem ----
    const int lane = tid & 31;
    const int warp = tid >> 5;          // quarter h = warp>>1
    __shared__ float sm[8][GBQ];
#pragma unroll
    for (int g = 0; g < GBQ; g++) {
        float v = acc[g];
#pragma unroll
        for (int o = 16; o > 0; o >>= 1) v += __shfl_down_sync(0xffffffffu, v, o);
        if (lane == 0) sm[warp][g] = v;
    }
    __syncthreads();

    // chunk constant: sum of this chunk's 16 g_row entries (warp 0)
    float chunkC = 0.0f;
    if (warp == 0) {
        float v = (lane < CHUNK) ? g_row[tstart + lane] : 0.0f;
#pragma unroll
        for (int o = 16; o > 0; o >>= 1) v += __shfl_down_sync(0xffffffffu, v, o);
        chunkC = __shfl_sync(0xffffffffu, v, 0);
    }

    if (tid < GBTOT) {
        int q = tid >> 2;       // quarter
        int g = tid & 3;        // batch within quarter
        float s = sm[q * 2 + 0][g] + sm[q * 2 + 1][g];
        atomicAdd(&out[bbase + q * GBQ + g], -0.5f * (s + chunkC));
    }
}

extern "C" void kernel_launch(void* const* d_in, const int* in_sizes, int n_in,
                              void* d_out, int out_size) {
    const float* y  = (const float*)d_in[0];
    const float* ts = (const float*)d_in[1];
    const float* mu = (const float*)d_in[2];
    const float* lk = (const float*)d_in[3];
    const float* ls = (const float*)d_in[4];
    float* out = (float*)d_out;

    k_precompute<<<TLEN, DDIM>>>(ts, lk, ls, mu, out, out_size);
    k_main<<<(BATCH / GBTOT) * NCHUNK, 256>>>(y, out);
}

// round 9
// speedup vs baseline: 1.0384x; 1.0384x over previous
#include <cuda_runtime.h>
#include <math.h>

// Problem shape (fixed by setup_inputs)
#define BATCH 256
#define TLEN  1024
#define DDIM  256
#define LOG2PI 1.8378770664093453f

// Main-kernel tiling
#define GBTOT   8                 // batches per block (4 quarters x 2, sequential)
#define NCHUNK  32                // t-chunks
#define CHUNK   (TLEN / NCHUNK)   // 32 (uniform: t=0 folded into table row 0)
#define BURST   8                 // t-rows per contiguous 8KB read burst
#define BSTRIDE (TLEN * DDIM)     // elements between batches (1MB)

// Table: 3 SoA sections of TLEN*DDIM floats; row 0 encodes the initial term
// (A=0, R=1/sqrt(var0), C=-mu/sqrt(var0)), rows t>=1 the transitions.
#define SEC    (TLEN * DDIM)
#define SEC_A  0
#define SEC_R  SEC
#define SEC_C  (2 * SEC)
__device__ float g_tabf[3 * SEC];
__device__ float g_row[TLEN];       // per-t row sums of log q + LOG2PI

__device__ __forceinline__ float softplusf(float x) {
    return (x > 20.f) ? x : log1pf(expf(x));
}

// ---------------------------------------------------------------------------
// Kernel 1: precompute table + per-row log constants; zero the output.
// grid = TLEN blocks, block = DDIM threads
// ---------------------------------------------------------------------------
__global__ void k_precompute(const float* __restrict__ ts,
                             const float* __restrict__ log_kappa,
                             const float* __restrict__ log_sigma,
                             const float* __restrict__ mu,
                             float* __restrict__ out, int out_size) {
    const int t = blockIdx.x;
    const int d = threadIdx.x;

    float kappa = softplusf(log_kappa[d]) + 1e-6f;
    float sigma = softplusf(log_sigma[d]) + 1e-6f;
    float s2 = sigma * sigma;
    float mu_d = mu[d];

    float elem;
    const int idx = t * DDIM + d;
    if (t == 0) {
        float var0 = fmaxf(s2 / (2.0f * kappa), 1e-10f);
        float r0 = rsqrtf(var0);
        g_tabf[SEC_A + idx] = 0.0f;          // zero out prev contribution
        g_tabf[SEC_R + idx] = r0;
        g_tabf[SEC_C + idx] = -mu_d * r0;
        elem = logf(var0) + LOG2PI;
        for (int i = d; i < out_size; i += blockDim.x) out[i] = 0.0f;
    } else {
        float dt = fmaxf(ts[t * DDIM + d] - ts[(t - 1) * DDIM + d], 1e-6f);
        float Ad = expf(-kappa * dt);
        float q  = fmaxf(s2 * (-expm1f(-2.0f * kappa * dt)) / (2.0f * kappa), 1e-10f);
        float R  = rsqrtf(q);
        g_tabf[SEC_A + idx] = Ad;
        g_tabf[SEC_R + idx] = R;
        g_tabf[SEC_C + idx] = -mu_d * (1.0f - Ad) * R;
        elem = logf(q) + LOG2PI;
    }

    __shared__ float sm[DDIM];
    sm[d] = elem;
    __syncthreads();
    for (int s = DDIM / 2; s > 0; s >>= 1) {
        if (d < s) sm[d] += sm[d + s];
        __syncthreads();
    }
    if (d == 0) g_row[t] = sm[0];
}

// ---------------------------------------------------------------------------
// Kernel 2: main streaming pass. grid = 1024 blocks, block = 256 threads.
// Quarter h = tid>>6 (64 threads, dq = tid&63 -> d = 4dq..4dq+3) handles
// batches {bbase+2h, bbase+2h+1} SEQUENTIALLY (depth-first): per batch, y is
// read in contiguous 8KB bursts (8 consecutive t-rows of LDG.128) from ONE
// stream, maximizing DRAM row-buffer locality (vs interleaving 8 far-apart
// streams at 1KB granularity). Table loads JIT (L1/L2 hits).
// ---------------------------------------------------------------------------
__global__ __launch_bounds__(256, 4)
void k_main(const float* __restrict__ y, float* __restrict__ out) {
    const int c     = blockIdx.x & (NCHUNK - 1);
    const int bbase = (blockIdx.x >> 5) * GBTOT;
    const int tid   = threadIdx.x;
    const int dq    = tid & 63;
    const int h     = tid >> 6;

    const int tstart = c * CHUNK;
    const int prow   = (c == 0) ? 0 : tstart - 1;  // value unused at c==0 (A=0)

    const float* __restrict__ yb =
        y + (size_t)(bbase + 2 * h) * BSTRIDE + 4 * dq;
    const float* __restrict__ tb = g_tabf + 4 * dq + (size_t)tstart * DDIM;

    float acc[2];

#pragma unroll
    for (int g = 0; g < 2; g++) {
        const float* __restrict__ ybg = yb + (size_t)g * BSTRIDE;
        float4 prev = __ldcs((const float4*)(ybg + (size_t)prow * DDIM));
        float accg = 0.0f;
        const float* __restrict__ yt = ybg + (size_t)tstart * DDIM;

#pragma unroll
        for (int i = 0; i < CHUNK / BURST; i++) {
            // ---- contiguous 8KB burst: 8 LDG.128 back-to-back, one stream ----
            float4 w[BURST];
#pragma unroll
            for (int u = 0; u < BURST; u++)
                w[u] = __ldcs((const float4*)(yt + (i * BURST + u) * DDIM));

            // ---- compute with JIT table loads ----
#pragma unroll
            for (int u = 0; u < BURST; u++) {
                const float* tt = tb + (i * BURST + u) * DDIM;
                float4 A  = __ldg((const float4*)(tt + SEC_A));
                float4 R  = __ldg((const float4*)(tt + SEC_R));
                float4 Cc = __ldg((const float4*)(tt + SEC_C));
                float x0 = fmaf(-A.x, prev.x, w[u].x);
                float x1 = fmaf(-A.y, prev.y, w[u].y);
                float x2 = fmaf(-A.z, prev.z, w[u].z);
                float x3 = fmaf(-A.w, prev.w, w[u].w);
                float z0 = fmaf(x0, R.x, Cc.x);
                float z1 = fmaf(x1, R.y, Cc.y);
                float z2 = fmaf(x2, R.z, Cc.z);
                float z3 = fmaf(x3, R.w, Cc.w);
                accg = fmaf(z0, z0, accg);
                accg = fmaf(z1, z1, accg);
                accg = fmaf(z2, z2, accg);
                accg = fmaf(z3, z3, accg);
                prev = w[u];
            }
        }
        acc[g] = accg;
    }

    // ---- reduce: warp shuffle per g, cross-warp via smem ----
    const int lane = tid & 31;
    const int warp = tid >> 5;          // quarter h = warp>>1
    __shared__ float sm[8][2];
#pragma unroll
    for (int g = 0; g < 2; g++) {
        float v = acc[g];
#pragma unroll
        for (int o = 16; o > 0; o >>= 1) v += __shfl_down_sync(0xffffffffu, v, o);
        if (lane == 0) sm[warp][g] = v;
    }
    __syncthreads();

    // chunk constant: sum of this chunk's 32 g_row entries (warp 0)
    float chunkC = 0.0f;
    if (warp == 0) {
        float v = g_row[tstart + lane];
#pragma unroll
        for (int o = 16; o > 0; o >>= 1) v += __shfl_down_sync(0xffffffffu, v, o);
        chunkC = __shfl_sync(0xffffffffu, v, 0);
    }

    if (tid < GBTOT) {
        int q = tid >> 1;       // quarter
        int g = tid & 1;        // batch within quarter
        float s = sm[q * 2 + 0][g] + sm[q * 2 + 1][g];
        atomicAdd(&out[bbase + 2 * q + g], -0.5f * (s + chunkC));
    }
}

extern "C" void kernel_launch(void* const* d_in, const int* in_sizes, int n_in,
                              void* d_out, int out_size) {
    const float* y  = (const float*)d_in[0];
    const float* ts = (const float*)d_in[1];
    const float* mu = (const float*)d_in[2];
    const float* lk = (const float*)d_in[3];
    const float* ls = (const float*)d_in[4];
    float* out = (float*)d_out;

    k_precompute<<<TLEN, DDIM>>>(ts, lk, ls, mu, out, out_size);
    k_main<<<(BATCH / GBTOT) * NCHUNK, 256>>>(y, out);
}